// round 2
// baseline (speedup 1.0000x reference)
#include <cuda_runtime.h>
#include <cstddef>

#define N_ROWS 8192
#define N_COLS 8192
#define THREADS 256
#define N_STEPS 100
#define SPG 25              // steps per warp-pair group (4 groups x 25 = 100)
#define EPT (N_COLS / 64)   // elements per thread within a 64-thread group = 128

__global__ __launch_bounds__(THREADS)
void mse_observer_kernel(const float* __restrict__ x, float* __restrict__ out) {
    __shared__ float row_sm[N_COLS];
    __shared__ float invs[N_STEPS];     // 1/scale_i
    __shared__ float s2k[N_STEPS];      // scale_i^2 / 8192
    __shared__ float thr_sm[N_STEPS];   // thres_i
    __shared__ float partial[8][SPG];   // per-warp partial sums
    __shared__ float red_min[8], red_max[8];
    __shared__ float losses[N_STEPS];
    __shared__ float Rsh, rmin_sh, rmax_sh;

    const int row  = blockIdx.x;
    const int tid  = threadIdx.x;
    const int warp = tid >> 5;
    const int lane = tid & 31;
    const float* xr = x + (size_t)row * N_COLS;

    // ---- Phase A: load row to smem, compute row min/max ----
    float mn = 3.0e38f, mx = -3.0e38f;
    const float4* xr4 = (const float4*)xr;
    float4* row4 = (float4*)row_sm;
    #pragma unroll
    for (int k = 0; k < N_COLS / 4 / THREADS; k++) {   // 8 iterations
        float4 v = xr4[tid + k * THREADS];
        row4[tid + k * THREADS] = v;
        mn = fminf(mn, fminf(fminf(v.x, v.y), fminf(v.z, v.w)));
        mx = fmaxf(mx, fmaxf(fmaxf(v.x, v.y), fmaxf(v.z, v.w)));
    }
    #pragma unroll
    for (int o = 16; o; o >>= 1) {
        mn = fminf(mn, __shfl_xor_sync(0xFFFFFFFFu, mn, o));
        mx = fmaxf(mx, __shfl_xor_sync(0xFFFFFFFFu, mx, o));
    }
    if (lane == 0) { red_min[warp] = mn; red_max[warp] = mx; }
    __syncthreads();
    if (tid == 0) {
        float m = red_min[0], M = red_max[0];
        #pragma unroll
        for (int w = 1; w < 8; w++) { m = fminf(m, red_min[w]); M = fmaxf(M, red_max[w]); }
        rmin_sh = m; rmax_sh = M;
        Rsh = fmaxf(fabsf(m), M);   // range_val = max(|min|, max)
    }
    __syncthreads();

    // ---- Phase B: per-step tables ----
    if (tid < N_STEPS) {
        float R = Rsh;
        float thres = __fdiv_rn(R, 100.0f) * (float)(tid + 1);
        float scale = fmaxf(__fdiv_rn(thres, 127.5f), 1.1920928955078125e-07f);
        thr_sm[tid] = thres;
        invs[tid]   = __fdiv_rn(1.0f, scale);
        s2k[tid]    = scale * scale * (1.0f / 8192.0f);
    }
    __syncthreads();

    // ---- Phase C: main compute. Group g = warp/2 owns steps [g*25, g*25+25).
    // err = (clip(round(x/s))*s - x)^2 = s^2 * (clip(round(t)) - t)^2, t = x*inv.
    // round via magic constant (round-half-even, valid for all t here since
    // |t| > 127.5 is clamped anyway).
    const int grp  = tid >> 6;
    const int l64  = tid & 63;
    const int base = grp * SPG;
    const float MAGIC = 12582912.0f;   // 1.5 * 2^23

    float invr[SPG], acc[SPG];
    #pragma unroll
    for (int j = 0; j < SPG; j++) { invr[j] = invs[base + j]; acc[j] = 0.0f; }

    #pragma unroll 2
    for (int k = 0; k < EPT; k++) {
        float xv = row_sm[l64 + (k << 6)];
        #pragma unroll
        for (int j = 0; j < SPG; j++) {
            float r = __fmaf_rn(xv, invr[j], MAGIC);   // t + MAGIC
            float q = __fadd_rn(r, -MAGIC);            // round(t), half-even
            q = fminf(q, 127.0f);
            q = fmaxf(q, -128.0f);
            float d = __fmaf_rn(xv, invr[j], -q);      // t - q
            acc[j] = __fmaf_rn(d, d, acc[j]);
        }
    }

    // ---- Phase D: deterministic reductions ----
    #pragma unroll
    for (int j = 0; j < SPG; j++) {
        float v = acc[j];
        #pragma unroll
        for (int o = 16; o; o >>= 1) v += __shfl_xor_sync(0xFFFFFFFFu, v, o);
        if (lane == 0) partial[warp][j] = v;
    }
    __syncthreads();
    if (tid < N_STEPS) {
        int g = tid / SPG, jj = tid - g * SPG;
        float sum = partial[2 * g][jj] + partial[2 * g + 1][jj];
        losses[tid] = sum * s2k[tid];   // mean((xq-x)^2)
    }
    __syncthreads();

    // ---- Phase E: sequential argmin scan (matches lax.scan semantics) ----
    if (tid == 0) {
        float best = 1.0e9f;
        float bmin = rmin_sh, bmax = rmax_sh;
        for (int j = 0; j < N_STEPS; j++) {
            float L = losses[j];
            if (L < best) { best = L; bmin = -thr_sm[j]; bmax = thr_sm[j]; }
        }
        out[row] = bmin;
        out[N_ROWS + row] = bmax;
    }
}

extern "C" void kernel_launch(void* const* d_in, const int* in_sizes, int n_in,
                              void* d_out, int out_size) {
    const float* x = (const float*)d_in[0];
    float* out = (float*)d_out;
    mse_observer_kernel<<<N_ROWS, THREADS>>>(x, out);
}

// round 3
// speedup vs baseline: 1.1771x; 1.1771x over previous
#include <cuda_runtime.h>
#include <cstddef>

#define N_ROWS 8192
#define N_COLS 8192
#define THREADS 256
#define N_STEPS 100
#define SPG 25              // steps per 64-thread group (4 groups x 25 = 100)
#define NPAIR 12            // 12 packed step-pairs + 1 scalar step = 25
#define EPT (N_COLS / 64)   // elements per thread within a 64-thread group = 128

__global__ __launch_bounds__(THREADS)
void mse_observer_kernel(const float* __restrict__ x, float* __restrict__ out) {
    __shared__ float row_sm[N_COLS];
    __shared__ float invs[N_STEPS];     // 1/scale_i
    __shared__ float s2k[N_STEPS];      // scale_i^2 / 8192
    __shared__ float thr_sm[N_STEPS];   // thres_i
    __shared__ float partial[8][SPG];   // per-warp partial sums
    __shared__ float red_min[8], red_max[8];
    __shared__ float losses[N_STEPS];
    __shared__ float Rsh, rmin_sh, rmax_sh;

    const int row  = blockIdx.x;
    const int tid  = threadIdx.x;
    const int warp = tid >> 5;
    const int lane = tid & 31;
    const float* xr = x + (size_t)row * N_COLS;

    // ---- Phase A: load row to smem, compute row min/max ----
    float mn = 3.0e38f, mx = -3.0e38f;
    const float4* xr4 = (const float4*)xr;
    float4* row4 = (float4*)row_sm;
    #pragma unroll
    for (int k = 0; k < N_COLS / 4 / THREADS; k++) {   // 8 iterations
        float4 v = xr4[tid + k * THREADS];
        row4[tid + k * THREADS] = v;
        mn = fminf(mn, fminf(fminf(v.x, v.y), fminf(v.z, v.w)));
        mx = fmaxf(mx, fmaxf(fmaxf(v.x, v.y), fmaxf(v.z, v.w)));
    }
    #pragma unroll
    for (int o = 16; o; o >>= 1) {
        mn = fminf(mn, __shfl_xor_sync(0xFFFFFFFFu, mn, o));
        mx = fmaxf(mx, __shfl_xor_sync(0xFFFFFFFFu, mx, o));
    }
    if (lane == 0) { red_min[warp] = mn; red_max[warp] = mx; }
    __syncthreads();
    if (tid == 0) {
        float m = red_min[0], M = red_max[0];
        #pragma unroll
        for (int w = 1; w < 8; w++) { m = fminf(m, red_min[w]); M = fmaxf(M, red_max[w]); }
        rmin_sh = m; rmax_sh = M;
        Rsh = fmaxf(fabsf(m), M);   // range_val = max(|min|, max)
    }
    __syncthreads();

    // ---- Phase B: per-step tables ----
    if (tid < N_STEPS) {
        float R = Rsh;
        float thres = __fdiv_rn(R, 100.0f) * (float)(tid + 1);
        float scale = fmaxf(__fdiv_rn(thres, 127.5f), 1.1920928955078125e-07f);
        thr_sm[tid] = thres;
        invs[tid]   = __fdiv_rn(1.0f, scale);
        s2k[tid]    = scale * scale * (1.0f / 8192.0f);
    }
    __syncthreads();

    // ---- Phase C: main compute, packed f32x2 over step-pairs.
    // err = s^2 * (t - clip(round(t)))^2, t = x*inv.
    // round(t) via magic constant M=1.5*2^23: r = fma(x,inv,M) = M + round(t) EXACT.
    // nq = fma(r,-1,M) = -round(t) EXACT; clamp -q to [-127,128];
    // d = fma(x,inv,nq) = t - q;  acc += d*d.  All packed 2 steps/lane.
    const int grp  = tid >> 6;
    const int l64  = tid & 63;
    const int base = grp * SPG;
    const float MAGIC = 12582912.0f;   // 1.5 * 2^23
    const unsigned long long MAGIC2 = 0x4B4000004B400000ULL;  // {MAGIC, MAGIC}
    const unsigned long long NEG1x2 = 0xBF800000BF800000ULL;  // {-1.0f, -1.0f}

    unsigned long long ivp[NPAIR], app[NPAIR];
    #pragma unroll
    for (int j = 0; j < NPAIR; j++) {
        float a = invs[base + 2 * j], b = invs[base + 2 * j + 1];
        asm("mov.b64 %0, {%1,%2};" : "=l"(ivp[j]) : "f"(a), "f"(b));
        app[j] = 0ULL;
    }
    float inv_last = invs[base + 24];
    float acc_last = 0.0f;

    #pragma unroll 2
    for (int k = 0; k < EPT; k++) {
        float xv = row_sm[l64 + (k << 6)];
        unsigned long long xx;
        asm("mov.b64 %0, {%1,%1};" : "=l"(xx) : "f"(xv));
        #pragma unroll
        for (int j = 0; j < NPAIR; j++) {
            asm("{\n\t"
                ".reg .f32 n0,n1;\n\t"
                ".reg .b64 rr,nq,dd;\n\t"
                "fma.rn.f32x2 rr, %1, %2, %3;\n\t"   // M + round(t)
                "fma.rn.f32x2 nq, rr, %4, %3;\n\t"   // -round(t)  (exact)
                "mov.b64 {n0,n1}, nq;\n\t"
                "max.f32 n0, n0, 0fC2FE0000;\n\t"    // -127
                "min.f32 n0, n0, 0f43000000;\n\t"    // 128
                "max.f32 n1, n1, 0fC2FE0000;\n\t"
                "min.f32 n1, n1, 0f43000000;\n\t"
                "mov.b64 nq, {n0,n1};\n\t"
                "fma.rn.f32x2 dd, %1, %2, nq;\n\t"   // t - q
                "fma.rn.f32x2 %0, dd, dd, %0;\n\t"   // acc += d*d
                "}"
                : "+l"(app[j])
                : "l"(xx), "l"(ivp[j]), "l"(MAGIC2), "l"(NEG1x2));
        }
        // scalar leftover step (index base+24)
        float r  = __fmaf_rn(xv, inv_last, MAGIC);
        float nq = MAGIC - r;
        nq = fmaxf(nq, -127.0f);
        nq = fminf(nq, 128.0f);
        float d = __fmaf_rn(xv, inv_last, nq);
        acc_last = __fmaf_rn(d, d, acc_last);
    }

    // ---- Phase D: deterministic reductions ----
    #pragma unroll
    for (int j = 0; j < NPAIR; j++) {
        float a0, a1;
        asm("mov.b64 {%0,%1}, %2;" : "=f"(a0), "=f"(a1) : "l"(app[j]));
        #pragma unroll
        for (int o = 16; o; o >>= 1) {
            a0 += __shfl_xor_sync(0xFFFFFFFFu, a0, o);
            a1 += __shfl_xor_sync(0xFFFFFFFFu, a1, o);
        }
        if (lane == 0) { partial[warp][2 * j] = a0; partial[warp][2 * j + 1] = a1; }
    }
    {
        float v = acc_last;
        #pragma unroll
        for (int o = 16; o; o >>= 1) v += __shfl_xor_sync(0xFFFFFFFFu, v, o);
        if (lane == 0) partial[warp][24] = v;
    }
    __syncthreads();
    if (tid < N_STEPS) {
        int g = tid / SPG, jj = tid - g * SPG;
        float sum = partial[2 * g][jj] + partial[2 * g + 1][jj];
        losses[tid] = sum * s2k[tid];   // mean((xq-x)^2)
    }
    __syncthreads();

    // ---- Phase E: sequential argmin scan (matches lax.scan semantics) ----
    if (tid == 0) {
        float best = 1.0e9f;
        float bmin = rmin_sh, bmax = rmax_sh;
        for (int j = 0; j < N_STEPS; j++) {
            float L = losses[j];
            if (L < best) { best = L; bmin = -thr_sm[j]; bmax = thr_sm[j]; }
        }
        out[row] = bmin;
        out[N_ROWS + row] = bmax;
    }
}

extern "C" void kernel_launch(void* const* d_in, const int* in_sizes, int n_in,
                              void* d_out, int out_size) {
    const float* x = (const float*)d_in[0];
    float* out = (float*)d_out;
    mse_observer_kernel<<<N_ROWS, THREADS>>>(x, out);
}